// round 17
// baseline (speedup 1.0000x reference)
#include <cuda_runtime.h>
#include <cuda_fp16.h>
#include <cstdint>

// ---------------- problem constants ----------------
#define BATCH 2
#define DDIM  8
#define HPX   56
#define WPX   56
#define CDIM  256
#define NTOK  (BATCH*DDIM*HPX*WPX)   // 50176
#define NSPAT (DDIM*HPX*WPX)         // 25088
#define NWIN  98
#define NBIAS 1575
#define MLPD  1024

// ---------------- scratch ----------------
__device__ float g_y  [NTOK*CDIM];        // residual stream, fp32
__device__ __half g_qkvh[NTOK*3*CDIM];    // qkv projections fp16
__device__ __half g_a[NTOK*CDIM];         // activations fp16 (LN out / attn out)
__device__ __half g_b[NTOK*MLPD];         // gelu out (fc2 input)
// transposed fp16 weights: [M_out, K] K-major
__device__ __half w_qkv[4*768*256];
__device__ __half w_out[4*256*256];
__device__ __half w_fc1[4*1024*256];
__device__ __half w_fc2[4*256*1024];

// ---------------- helpers ----------------
__device__ __forceinline__ uint32_t smem_u32(const void* p){
    uint32_t a;
    asm("{ .reg .u64 t; cvta.to.shared.u64 t, %1; cvt.u32.u64 %0, t; }" : "=r"(a) : "l"(p));
    return a;
}
__device__ __forceinline__ void cp16(uint32_t dst, const void* src){
    asm volatile("cp.async.cg.shared.global [%0], [%1], 16;" :: "r"(dst), "l"(src));
}
__device__ __forceinline__ void cp_commit(){
    asm volatile("cp.async.commit_group;" ::: "memory");
}
template<int N>
__device__ __forceinline__ void cp_wait(){
    asm volatile("cp.async.wait_group %0;" :: "n"(N) : "memory");
}
__device__ __forceinline__ void ldsm4(uint32_t addr, uint32_t* r){
    asm volatile("ldmatrix.sync.aligned.m8n8.x4.shared.b16 {%0,%1,%2,%3}, [%4];"
        : "=r"(r[0]), "=r"(r[1]), "=r"(r[2]), "=r"(r[3]) : "r"(addr));
}
__device__ __forceinline__ void ldsm4t(uint32_t addr, uint32_t* r){
    asm volatile("ldmatrix.sync.aligned.m8n8.x4.trans.shared.b16 {%0,%1,%2,%3}, [%4];"
        : "=r"(r[0]), "=r"(r[1]), "=r"(r[2]), "=r"(r[3]) : "r"(addr));
}
__device__ __forceinline__ void mma16816h(float* c, const uint32_t* a, uint32_t b0, uint32_t b1){
    asm volatile("mma.sync.aligned.m16n8k16.row.col.f32.f16.f16.f32 "
        "{%0,%1,%2,%3}, {%4,%5,%6,%7}, {%8,%9}, {%0,%1,%2,%3};"
        : "+f"(c[0]), "+f"(c[1]), "+f"(c[2]), "+f"(c[3])
        : "r"(a[0]), "r"(a[1]), "r"(a[2]), "r"(a[3]), "r"(b0), "r"(b1));
}
__device__ __forceinline__ float gelu_tanh(float x){
    float x3 = x*x*x;
    return 0.5f*x*(1.f + tanhf(0.7978845608028654f*(x + 0.044715f*x3)));
}

// ---------------- weight prep: W[K,M] fp32 -> Wt[M,K] fp16 ----------------
__global__ void wprep_kernel(const float* __restrict__ W, __half* __restrict__ oh,
                             int K, int M)
{
    int ly = blockIdx.y;
    size_t n = (size_t)K*M;
    const float* w = W + ly*n;
    __half* h = oh + ly*n;
    for (size_t i = (size_t)blockIdx.x*blockDim.x + threadIdx.x; i < n; i += (size_t)gridDim.x*blockDim.x){
        int k = (int)(i / M), m = (int)(i % M);
        h[(size_t)m*K + k] = __float2half_rn(w[i]);
    }
}

// ---------------- patch embed ----------------
__global__ void patch_embed_kernel(const float* __restrict__ x,
                                   const float* __restrict__ w,
                                   const float* __restrict__ b,
                                   float* __restrict__ y)
{
    int t = blockIdx.x;
    int wp = t % WPX, hp = (t/WPX) % HPX, d = (t/(WPX*HPX)) % DDIM, bb = t/(WPX*HPX*DDIM);
    __shared__ float patch[64];
    int tid = threadIdx.x;
    if (tid < 64){
        int ic = tid>>4, kh = (tid>>2)&3, kw = tid&3;
        patch[tid] = x[ (((size_t)(bb*4+ic)*DDIM + d)*224 + hp*4+kh)*224 + wp*4+kw ];
    }
    __syncthreads();
    float acc = b[tid];
    const float* wr = w + tid*64;
    #pragma unroll
    for (int k=0;k<64;k++) acc += patch[k]*wr[k];
    y[(size_t)t*CDIM + tid] = acc;
}

// ---------------- layernorm: warp per token, 8 tokens/block, fp16 out ----------------
__global__ void ln_kernel(const float* __restrict__ in,
                          __half* __restrict__ oh,
                          const float* __restrict__ sc, const float* __restrict__ bi)
{
    int warp = threadIdx.x >> 5, lane = threadIdx.x & 31;
    int t = blockIdx.x*8 + warp;
    const float4* row = (const float4*)(in + (size_t)t*CDIM);
    float4 a = row[lane*2], b = row[lane*2+1];
    float s1 = a.x+a.y+a.z+a.w + b.x+b.y+b.z+b.w;
    float s2 = a.x*a.x+a.y*a.y+a.z*a.z+a.w*a.w + b.x*b.x+b.y*b.y+b.z*b.z+b.w*b.w;
    #pragma unroll
    for (int o=16;o;o>>=1){
        s1 += __shfl_xor_sync(0xffffffffu, s1, o);
        s2 += __shfl_xor_sync(0xffffffffu, s2, o);
    }
    float mean = s1*(1.f/256.f);
    float var  = s2*(1.f/256.f) - mean*mean;
    float rs = rsqrtf(var + 1e-5f);
    int c0 = lane*8;
    float4 sca = *(const float4*)(sc + c0), scb = *(const float4*)(sc + c0 + 4);
    float4 bia = *(const float4*)(bi + c0), bib = *(const float4*)(bi + c0 + 4);
    __half2 hh[4];
    hh[0] = __floats2half2_rn((a.x-mean)*rs*sca.x+bia.x, (a.y-mean)*rs*sca.y+bia.y);
    hh[1] = __floats2half2_rn((a.z-mean)*rs*sca.z+bia.z, (a.w-mean)*rs*sca.w+bia.w);
    hh[2] = __floats2half2_rn((b.x-mean)*rs*scb.x+bib.x, (b.y-mean)*rs*scb.y+bib.y);
    hh[3] = __floats2half2_rn((b.z-mean)*rs*scb.z+bib.z, (b.w-mean)*rs*scb.w+bib.w);
    *(uint4*)(oh + (size_t)t*CDIM + c0) = *(uint4*)hh;
}

// ---------------- B-resident persistent GEMM (K=256 only) ----------------
// A: [NTOK, 256] fp16 K-major. B: [M, 256] fp16 K-major.
// CTA owns a 128-col strip of B, full K=256 in smem (64KB), and processes RB
// row-blocks of 128 tokens, double-buffering A (2x64KB). 1 CTA/SM, 192KB smem.
// Warp grid 4m x 2n, warp tile 32x64. 512B smem rows, XOR-swizzled chunks.
// MODE 2: bias+residual fp32. MODE 3: bias+gelu -> fp16. MODE 4: fp16 out.
#define BG_B     0
#define BG_A0    65536
#define BG_TOTAL 196608

template<int MODE, int RB>
__global__ void __launch_bounds__(256, 1)
bgemm_kernel(const __half* __restrict__ A, const __half* __restrict__ B,
             const float* __restrict__ bias, float* __restrict__ C,
             __half* __restrict__ Oh, int M)
{
    extern __shared__ char smem[];
    uint32_t sb = smem_u32(smem);
    int tid = threadIdx.x, lane = tid & 31, wid = tid >> 5;
    int wm = wid & 3, wn = wid >> 2;
    int col0 = blockIdx.x*128;
    int rowg0 = blockIdx.y*RB;

    int lrow = lane & 15, lch = lane >> 4;

    // fill B strip (128 x 256 halfs = 4096 uint4) + A block 0
    {
        const __half* gB = B + (size_t)col0*256;
        const __half* gA = A + (size_t)rowg0*128*256;
        #pragma unroll
        for (int h=0; h<16; h++){
            int i = tid + (h<<8);
            int r = i>>5, ch = i&31;
            uint32_t doff = (r<<9) + ((ch ^ (r&7))<<4);
            cp16(sb + BG_B  + doff, gB + (size_t)r*256 + (ch<<3));
            cp16(sb + BG_A0 + doff, gA + (size_t)r*256 + (ch<<3));
        }
        cp_commit();
        cp_wait<0>();
    }
    __syncthreads();

    uint32_t tB = sb + BG_B;

    #pragma unroll 1
    for (int rb = 0; rb < RB; rb++){
        // prefetch next A block into alternate buffer
        if (rb+1 < RB){
            const __half* gA = A + (size_t)(rowg0+rb+1)*128*256;
            uint32_t bb = sb + BG_A0 + ((rb+1)&1)*65536;
            #pragma unroll
            for (int h=0; h<16; h++){
                int i = tid + (h<<8);
                int r = i>>5, ch = i&31;
                uint32_t doff = (r<<9) + ((ch ^ (r&7))<<4);
                cp16(bb + doff, gA + (size_t)r*256 + (ch<<3));
            }
            cp_commit();
        }

        uint32_t tA = sb + BG_A0 + (rb&1)*65536;

        float acc[2][8][4];
        #pragma unroll
        for (int i=0;i<2;i++)
            #pragma unroll
            for (int j=0;j<8;j++)
                #pragma unroll
                for (int k=0;k<4;k++) acc[i][j][k]=0.f;

        // full K=256: 16 ksteps, no intermediate syncs
        #pragma unroll
        for (int ks = 0; ks < 16; ks++){
            int ch0 = ks*2 + lch;
            uint32_t a_f[2][4], b_f[4][4];
            #pragma unroll
            for (int mt=0; mt<2; mt++){
                int row = wm*32 + mt*16 + lrow;
                uint32_t off = (row<<9) + ((ch0 ^ (row&7))<<4);
                ldsm4(tA + off, a_f[mt]);
            }
            #pragma unroll
            for (int np=0; np<4; np++){
                int row = wn*64 + np*16 + lrow;
                uint32_t off = (row<<9) + ((ch0 ^ (row&7))<<4);
                ldsm4(tB + off, b_f[np]);
            }
            #pragma unroll
            for (int mt=0; mt<2; mt++){
                #pragma unroll
                for (int nt=0; nt<8; nt++){
                    int np = nt>>1, hf = nt&1;
                    mma16816h(acc[mt][nt], a_f[mt], b_f[np][hf], b_f[np][hf+2]);
                }
            }
        }

        // epilogue for this row-block
        int row0 = (rowg0+rb)*128;
        int lr = lane >> 2, lc2 = (lane & 3) * 2;
        #pragma unroll
        for (int mt=0; mt<2; mt++){
            #pragma unroll
            for (int nt=0; nt<8; nt++){
                int col = col0 + wn*64 + nt*8 + lc2;
                #pragma unroll
                for (int half=0; half<2; half++){
                    int row = row0 + wm*32 + mt*16 + lr + half*8;
                    float v0 = acc[mt][nt][half*2+0];
                    float v1 = acc[mt][nt][half*2+1];
                    if (MODE == 2){
                        float2* cp = (float2*)(C + (size_t)row*M + col);
                        float2 o = *cp;
                        float2 r;
                        r.x = v0 + bias[col+0] + o.x;
                        r.y = v1 + bias[col+1] + o.y;
                        *cp = r;
                    } else if (MODE == 4){
                        *(__half2*)(Oh + (size_t)row*M + col) = __floats2half2_rn(v0, v1);
                    } else {
                        float a = gelu_tanh(v0 + bias[col+0]);
                        float b = gelu_tanh(v1 + bias[col+1]);
                        *(__half2*)(Oh + (size_t)row*M + col) = __floats2half2_rn(a, b);
                    }
                }
            }
        }

        if (rb+1 < RB) cp_wait<0>();
        __syncthreads();
    }
}

// ---------------- chunked GEMM (fc2: K=1024) ----------------
#define MG_STAGE 32768
#define MG_TOTAL 65536

template<int MODE>
__global__ void __launch_bounds__(256, 2)
mgemm_kernel(const __half* __restrict__ A,
             const __half* __restrict__ B,
             const float* __restrict__ bias, float* __restrict__ C,
             __half* __restrict__ Oh,
             int M, int K)
{
    extern __shared__ char smem[];
    uint32_t sb = smem_u32(smem);
    int tid = threadIdx.x, lane = tid & 31, wid = tid >> 5;
    int wm = wid & 3, wn = wid >> 2;
    int row0 = blockIdx.y*128, col0 = blockIdx.x*128;

    const __half* gA = A + (size_t)row0*K;
    const __half* gB = B + (size_t)col0*K;

    float acc[2][8][4];
    #pragma unroll
    for (int i=0;i<2;i++)
        #pragma unroll
        for (int j=0;j<8;j++)
            #pragma unroll
            for (int k=0;k<4;k++) acc[i][j][k]=0.f;

    int lrow = lane & 15, lch = lane >> 4;
    int nchunk = K >> 6;

    {
        uint32_t bb = sb;
        #pragma unroll
        for (int h=0; h<4; h++){
            int i = tid + (h<<8);
            int r = i>>3, ch = i&7;
            uint32_t doff = (r<<7) + ((ch ^ (r&7))<<4);
            cp16(bb +         doff, gA + (size_t)r*K + (ch<<3));
            cp16(bb + 16384 + doff, gB + (size_t)r*K + (ch<<3));
        }
        cp_commit();
    }

    #pragma unroll 1
    for (int c = 0; c < nchunk; c++){
        if (c+1 < nchunk){
            int k0 = (c+1) << 6;
            uint32_t bb = sb + ((c+1)&1)*MG_STAGE;
            #pragma unroll
            for (int h=0; h<4; h++){
                int i = tid + (h<<8);
                int r = i>>3, ch = i&7;
                uint32_t doff = (r<<7) + ((ch ^ (r&7))<<4);
                cp16(bb +         doff, gA + (size_t)r*K + k0 + (ch<<3));
                cp16(bb + 16384 + doff, gB + (size_t)r*K + k0 + (ch<<3));
            }
            cp_commit();
            cp_wait<1>();
        } else {
            cp_wait<0>();
        }
        __syncthreads();

        uint32_t tb = sb + (c&1)*MG_STAGE;
        uint32_t tA = tb, tB = tb + 16384;

        #pragma unroll
        for (int ks = 0; ks < 4; ks++){
            int ch0 = ks*2 + lch;
            uint32_t a_f[2][4], b_f[4][4];
            #pragma unroll
            for (int mt=0; mt<2; mt++){
                int row = wm*32 + mt*16 + lrow;
                uint32_t off = (row<<7) + ((ch0 ^ (row&7))<<4);
                ldsm4(tA + off, a_f[mt]);
            }
            #pragma unroll
            for (int np=0; np<4; np++){
                int row = wn*64 + np*16 + lrow;
                uint32_t off = (row<<7) + ((ch0 ^ (row&7))<<4);
                ldsm4(tB + off, b_f[np]);
            }
            #pragma unroll
            for (int mt=0; mt<2; mt++){
                #pragma unroll
                for (int nt=0; nt<8; nt++){
                    int np = nt>>1, hf = nt&1;
                    mma16816h(acc[mt][nt], a_f[mt], b_f[np][hf], b_f[np][hf+2]);
                }
            }
        }
        __syncthreads();
    }

    int lr = lane >> 2, lc = (lane & 3) * 2;
    #pragma unroll
    for (int mt=0; mt<2; mt++){
        #pragma unroll
        for (int nt=0; nt<8; nt++){
            int col = col0 + wn*64 + nt*8 + lc;
            #pragma unroll
            for (int half=0; half<2; half++){
                int row = row0 + wm*32 + mt*16 + lr + half*8;
                float v0 = acc[mt][nt][half*2+0];
                float v1 = acc[mt][nt][half*2+1];
                if (MODE == 2){
                    float2* cp = (float2*)(C + (size_t)row*M + col);
                    float2 o = *cp;
                    float2 r;
                    r.x = v0 + bias[col+0] + o.x;
                    r.y = v1 + bias[col+1] + o.y;
                    *cp = r;
                } else if (MODE == 4){
                    *(__half2*)(Oh + (size_t)row*M + col) = __floats2half2_rn(v0, v1);
                } else {
                    float a = gelu_tanh(v0 + bias[col+0]);
                    float b = gelu_tanh(v1 + bias[col+1]);
                    *(__half2*)(Oh + (size_t)row*M + col) = __floats2half2_rn(a, b);
                }
            }
        }
    }
}

// ---------------- HMMA flash window attention (fp16 out) ----------------
__global__ void __launch_bounds__(256, 1)
attn_kernel(const __half* __restrict__ qkvh,
            const float* __restrict__ btab_g,
            __half* __restrict__ outh, int shifted)
{
    __shared__ __half Qs[256*40];
    __shared__ __half Ks[64*40];
    __shared__ __half Vs[64*40];
    __shared__ float  btab[NBIAS];
    __shared__ int    sreg[256];

    int head = blockIdx.y;
    int bw = blockIdx.x;
    int b = bw / NWIN, w = bw % NWIN;
    int wd = w/49, wh = (w/7)%7, ww = w%7;
    int tid = threadIdx.x, lane = tid & 31, warp = tid >> 5;
    int lr = lane >> 2, lc = lane & 3;

    {
        int i = tid;
        int di = i>>6, hi = (i>>3)&7, wi = i&7;
        int dr = wd*4+di, hr = wh*8+hi, wr = ww*8+wi;
        int rd = dr<4?0:(dr<6?1:2);
        int rh = hr<48?0:(hr<52?1:2);
        int rw = wr<48?0:(wr<52?1:2);
        sreg[i] = rd*9 + rh*3 + rw;
        int d=dr, h=hr, w2=wr;
        if (shifted){ d=(dr+2)&7; h=(hr+4)%HPX; w2=(wr+4)%WPX; }
        int tok = ((b*DDIM + d)*HPX + h)*WPX + w2;
        const uint4* src = (const uint4*)(qkvh + (size_t)tok*768 + head*32);
        uint4* dst = (uint4*)(Qs + i*40);
        dst[0]=src[0]; dst[1]=src[1]; dst[2]=src[2]; dst[3]=src[3];
    }
    for (int t=tid; t<NBIAS; t+=256) btab[t] = btab_g[t*8 + head];
    __syncthreads();

    uint32_t qbase = smem_u32(Qs), kbase = smem_u32(Ks), vbase = smem_u32(Vs);

    uint32_t qa[2][2][4];
    #pragma unroll
    for (int mt=0; mt<2; mt++)
        #pragma unroll
        for (int kt=0; kt<2; kt++){
            int r = warp*32 + mt*16 + (lane&15);
            ldsm4(qbase + r*80 + (kt*16 + (lane>>4)*8)*2, qa[mt][kt]);
        }

    int rbase0[4], rmyreg[4], rtok[4];
    #pragma unroll
    for (int q=0; q<4; q++){
        int mt = q>>1, hf = q&1;
        int i = warp*32 + mt*16 + lr + hf*8;
        int di = i>>6, hi = (i>>3)&7, wi = i&7;
        int dr = wd*4+di, hr = wh*8+hi, wr = ww*8+wi;
        int rd = dr<4?0:(dr<6?1:2);
        int rh = hr<48?0:(hr<52?1:2);
        int rw = wr<48?0:(wr<52?1:2);
        rmyreg[q] = rd*9 + rh*3 + rw;
        rbase0[q] = (di+3)*225 + (hi+7)*15 + (wi+7);
        int d=dr, h=hr, w2=wr;
        if (shifted){ d=(dr+2)&7; h=(hr+4)%HPX; w2=(wr+4)%WPX; }
        rtok[q] = ((b*DDIM + d)*HPX + h)*WPX + w2;
    }

    float mrow[4], lrow[4];
    #pragma unroll
    for (int q=0; q<4; q++){ mrow[q] = -1e30f; lrow[q] = 0.f; }
    float o[2][4][4];
    #pragma unroll
    for (int mt=0; mt<2; mt++)
        #pragma unroll
        for (int nt=0; nt<4; nt++)
            #pragma unroll
            for (int k=0;k<4;k++) o[mt][nt][k] = 0.f;

    const float scale = 0.17677669529663687f;

    #pragma unroll 1
    for (int c = 0; c < 4; c++){
        __syncthreads();
        {
            int r = tid>>2, part = tid&3;
            int j = c*64 + r;
            int hi = (j>>3)&7, wi = j&7;
            int dr = wd*4+c, hr = wh*8+hi, wr = ww*8+wi;
            int d=dr, h=hr, w2=wr;
            if (shifted){ d=(dr+2)&7; h=(hr+4)%HPX; w2=(wr+4)%WPX; }
            int tok = ((b*DDIM + d)*HPX + h)*WPX + w2;
            const uint4* kv = (const uint4*)(qkvh + (size_t)tok*768 + 256 + head*32);
            const uint4* vv = (const uint4*)(qkvh + (size_t)tok*768 + 512 + head*32);
            *(uint4*)(Ks + r*40 + part*8) = kv[part];
            *(uint4*)(Vs + r*40 + part*8) = vv[part];
        }
        __syncthreads();

        float S[2][8][4];
        #pragma unroll
        for (int mt=0;mt<2;mt++)
            #pragma unroll
            for (int jt=0;jt<8;jt++)
                #pragma unroll
                for (int k=0;k<4;k++) S[mt][jt][k]=0.f;

        #pragma unroll
        for (int p=0; p<4; p++){
            uint32_t kf[2][4];
            #pragma unroll
            for (int kt=0; kt<2; kt++){
                int r = p*16 + (lane&15);
                ldsm4(kbase + r*80 + (kt*16 + (lane>>4)*8)*2, kf[kt]);
            }
            #pragma unroll
            for (int mt=0; mt<2; mt++)
                #pragma unroll
                for (int s=0; s<2; s++)
                    #pragma unroll
                    for (int kt=0; kt<2; kt++)
                        mma16816h(S[mt][p*2+s], qa[mt][kt], kf[kt][s], kf[kt][s+2]);
        }

        float mc[4];
        #pragma unroll
        for (int q=0;q<4;q++) mc[q] = -1e30f;
        #pragma unroll
        for (int mt=0; mt<2; mt++)
            #pragma unroll
            for (int jt=0; jt<8; jt++)
                #pragma unroll
                for (int idx=0; idx<4; idx++){
                    int q = mt*2 + (idx>>1);
                    int e = idx&1;
                    int rel = rbase0[q] - c*225 - jt*15 - (2*lc + e);
                    float s = fmaf(S[mt][jt][idx], scale, btab[rel]);
                    if (shifted && sreg[c*64 + jt*8 + 2*lc + e] != rmyreg[q]) s = -1e9f;
                    S[mt][jt][idx] = s;
                    mc[q] = fmaxf(mc[q], s);
                }
        #pragma unroll
        for (int q=0;q<4;q++){
            mc[q] = fmaxf(mc[q], __shfl_xor_sync(0xffffffffu, mc[q], 1));
            mc[q] = fmaxf(mc[q], __shfl_xor_sync(0xffffffffu, mc[q], 2));
        }

        float corr[4], sumc[4];
        #pragma unroll
        for (int q=0;q<4;q++){
            float mn = fmaxf(mrow[q], mc[q]);
            corr[q] = __expf(mrow[q] - mn);
            mrow[q] = mn;
            sumc[q] = 0.f;
        }
        uint32_t pa[2][4][4];
        #pragma unroll
        for (int mt=0; mt<2; mt++)
            #pragma unroll
            for (int kt2=0; kt2<4; kt2++){
                int jtA = kt2*2, jtB = kt2*2+1;
                float pA0 = __expf(S[mt][jtA][0]-mrow[mt*2]);
                float pA1 = __expf(S[mt][jtA][1]-mrow[mt*2]);
                float pA2 = __expf(S[mt][jtA][2]-mrow[mt*2+1]);
                float pA3 = __expf(S[mt][jtA][3]-mrow[mt*2+1]);
                float pB0 = __expf(S[mt][jtB][0]-mrow[mt*2]);
                float pB1 = __expf(S[mt][jtB][1]-mrow[mt*2]);
                float pB2 = __expf(S[mt][jtB][2]-mrow[mt*2+1]);
                float pB3 = __expf(S[mt][jtB][3]-mrow[mt*2+1]);
                sumc[mt*2+0] += pA0 + pA1 + pB0 + pB1;
                sumc[mt*2+1] += pA2 + pA3 + pB2 + pB3;
                __half2 a0 = __floats2half2_rn(pA0, pA1);
                __half2 a1 = __floats2half2_rn(pA2, pA3);
                __half2 a2 = __floats2half2_rn(pB0, pB1);
                __half2 a3 = __floats2half2_rn(pB2, pB3);
                pa[mt][kt2][0] = *(uint32_t*)&a0;
                pa[mt][kt2][1] = *(uint32_t*)&a1;
                pa[mt][kt2][2] = *(uint32_t*)&a2;
                pa[mt][kt2][3] = *(uint32_t*)&a3;
            }
        #pragma unroll
        for (int q=0;q<4;q++){
            sumc[q] += __shfl_xor_sync(0xffffffffu, sumc[q], 1);
            sumc[q] += __shfl_xor_sync(0xffffffffu, sumc[q], 2);
            lrow[q] = lrow[q]*corr[q] + sumc[q];
        }
        #pragma unroll
        for (int mt=0; mt<2; mt++)
            #pragma unroll
            for (int nt=0; nt<4; nt++){
                o[mt][nt][0] *= corr[mt*2+0];
                o[mt][nt][1] *= corr[mt*2+0];
                o[mt][nt][2] *= corr[mt*2+1];
                o[mt][nt][3] *= corr[mt*2+1];
            }

        #pragma unroll
        for (int dp=0; dp<2; dp++){
            uint32_t vl[4][4];
            #pragma unroll
            for (int kt2=0; kt2<4; kt2++){
                uint32_t addr = vbase + (kt2*16 + ((lane>>3)&1)*8 + (lane&7))*80
                              + (dp*16 + (lane>>4)*8)*2;
                ldsm4t(addr, vl[kt2]);
            }
            #pragma unroll
            for (int s=0; s<2; s++){
                int nt = dp*2 + s;
                #pragma unroll
                for (int mt=0; mt<2; mt++)
                    #pragma unroll
                    for (int kt2=0; kt2<4; kt2++)
                        mma16816h(o[mt][nt], pa[mt][kt2], vl[kt2][2*s], vl[kt2][2*s+1]);
            }
        }
    }

    float inv[4];
    #pragma unroll
    for (int q=0;q<4;q++) inv[q] = 1.f/lrow[q];
    #pragma unroll
    for (int mt=0; mt<2; mt++)
        #pragma unroll
        for (int nt=0; nt<4; nt++){
            int col = head*32 + nt*8 + 2*lc;
            #pragma unroll
            for (int hf=0; hf<2; hf++){
                int q = mt*2 + hf;
                float v0 = o[mt][nt][hf*2+0]*inv[q];
                float v1 = o[mt][nt][hf*2+1]*inv[q];
                *(__half2*)(outh + (size_t)rtok[q]*CDIM + col) = __floats2half2_rn(v0, v1);
            }
        }
}

// ---------------- final transpose: tiled, coalesced ----------------
__global__ void to_out_kernel(const float* __restrict__ y, float* __restrict__ out)
{
    __shared__ float tile[32][33];
    int b = blockIdx.z;
    int c0 = blockIdx.y*32, s0 = blockIdx.x*32;
    int tx = threadIdx.x & 31, ty = threadIdx.x >> 5;
    #pragma unroll
    for (int i=0;i<4;i++)
        tile[ty + i*8][tx] = y[((size_t)b*NSPAT + s0 + ty + i*8)*CDIM + c0 + tx];
    __syncthreads();
    #pragma unroll
    for (int i=0;i<4;i++)
        out[((size_t)(b*CDIM + c0 + ty + i*8))*NSPAT + s0 + tx] = tile[tx][ty + i*8];
}

// ---------------- launch ----------------
extern "C" void kernel_launch(void* const* d_in, const int* in_sizes, int n_in,
                              void* d_out, int out_size)
{
    const float* x      = (const float*)d_in[0];
    const float* conv_w = (const float*)d_in[1];
    const float* conv_b = (const float*)d_in[2];
    const float* ln1_s  = (const float*)d_in[3];
    const float* ln1_b  = (const float*)d_in[4];
    const float* qkv_w  = (const float*)d_in[5];
    const float* out_w  = (const float*)d_in[6];
    const float* out_b  = (const float*)d_in[7];
    const float* bias_t = (const float*)d_in[8];
    const float* ln2_s  = (const float*)d_in[9];
    const float* ln2_b  = (const float*)d_in[10];
    const float* fc1_w  = (const float*)d_in[11];
    const float* fc1_b  = (const float*)d_in[12];
    const float* fc2_w  = (const float*)d_in[13];
    const float* fc2_b  = (const float*)d_in[14];
    float* out = (float*)d_out;

    cudaFuncSetAttribute(mgemm_kernel<2>, cudaFuncAttributeMaxDynamicSharedMemorySize, MG_TOTAL);
    cudaFuncSetAttribute((const void*)bgemm_kernel<2,4>, cudaFuncAttributeMaxDynamicSharedMemorySize, BG_TOTAL);
    cudaFuncSetAttribute((const void*)bgemm_kernel<3,8>, cudaFuncAttributeMaxDynamicSharedMemorySize, BG_TOTAL);
    cudaFuncSetAttribute((const void*)bgemm_kernel<4,8>, cudaFuncAttributeMaxDynamicSharedMemorySize, BG_TOTAL);

    float *gy;
    __half *gqkvh, *ga, *gb;
    __half *wq, *wo, *w1, *w2;
    cudaGetSymbolAddress((void**)&gy,    g_y);
    cudaGetSymbolAddress((void**)&gqkvh, g_qkvh);
    cudaGetSymbolAddress((void**)&ga,    g_a);
    cudaGetSymbolAddress((void**)&gb,    g_b);
    cudaGetSymbolAddress((void**)&wq,    w_qkv);
    cudaGetSymbolAddress((void**)&wo,    w_out);
    cudaGetSymbolAddress((void**)&w1,    w_fc1);
    cudaGetSymbolAddress((void**)&w2,    w_fc2);

    wprep_kernel<<<dim3(512,4), 256>>>(qkv_w, wq, 256, 768);
    wprep_kernel<<<dim3(512,4), 256>>>(out_w, wo, 256, 256);
    wprep_kernel<<<dim3(512,4), 256>>>(fc1_w, w1, 256, 1024);
    wprep_kernel<<<dim3(512,4), 256>>>(fc2_w, w2, 1024, 256);

    patch_embed_kernel<<<NTOK, 256>>>(x, conv_w, conv_b, gy);

    for (int L=0; L<4; L++){
        int shifted = L & 1;
        ln_kernel<<<NTOK/8, 256>>>(gy, ga, ln1_s + L*256, ln1_b + L*256);
        bgemm_kernel<4,8><<<dim3(6, 49), 256, BG_TOTAL>>>(ga,
            wq + (size_t)L*768*256, nullptr, nullptr, gqkvh, 768);
        attn_kernel<<<dim3(BATCH*NWIN, 8), 256>>>(gqkvh, bias_t + (size_t)L*NBIAS*8, ga, shifted);
        bgemm_kernel<2,4><<<dim3(2, 98), 256, BG_TOTAL>>>(ga,
            wo + (size_t)L*256*256, out_b + L*256, gy, nullptr, 256);
        ln_kernel<<<NTOK/8, 256>>>(gy, ga, ln2_s + L*256, ln2_b + L*256);
        bgemm_kernel<3,8><<<dim3(8, 49), 256, BG_TOTAL>>>(ga,
            w1 + (size_t)L*1024*256, fc1_b + L*1024, nullptr, gb, 1024);
        mgemm_kernel<2><<<dim3(2, 392), 256, MG_TOTAL>>>(gb,
            w2 + (size_t)L*256*1024, fc2_b + L*256, gy, nullptr, 256, 1024);
    }

    to_out_kernel<<<dim3(NSPAT/32, CDIM/32, BATCH), 256>>>(gy, out);
}